// round 1
// baseline (speedup 1.0000x reference)
#include <cuda_runtime.h>
#include <math.h>

#define NTOK 8192
#define DDIM 1024
#define APW  249            // APPERTURE - 1 : band is |i - j| <= 249
#define BANDW 512           // padded band width; valid t = j - i + 249 in [0, 498]

// ---------------- scratch (static device arrays; no allocation) ----------------
__device__ float g_Q [(size_t)NTOK * DDIM];
__device__ float g_K [(size_t)NTOK * DDIM];
__device__ float g_V [(size_t)NTOK * DDIM];
__device__ float g_Y0[(size_t)NTOK * DDIM];
__device__ float g_S [(size_t)NTOK * BANDW];

// =====================================================================
// C[M,Nn] = alpha * A[M,K] @ B[Nn,K]^T   (all row-major)
// 128x128 tile, BK=8, 256 threads, 8x8 per thread
// =====================================================================
__global__ __launch_bounds__(256) void gemm_nt_128(
    const float* __restrict__ A, const float* __restrict__ B,
    float* __restrict__ C, int M, int Nn, int K, float alpha)
{
    __shared__ float As[8][128];
    __shared__ float Bs[8][128];
    const int t  = threadIdx.x;
    const int tx = t & 15;          // N sub-tile
    const int ty = t >> 4;          // M sub-tile
    const int lr = t >> 1;          // load row 0..127
    const int lk = (t & 1) << 2;    // load k offset 0 or 4

    const float* Ab = A + (size_t)blockIdx.y * 128 * K + (size_t)lr * K + lk;
    const float* Bb = B + (size_t)blockIdx.x * 128 * K + (size_t)lr * K + lk;

    float acc[8][8] = {};

    for (int k0 = 0; k0 < K; k0 += 8) {
        float4 av = *(const float4*)(Ab + k0);
        float4 bv = *(const float4*)(Bb + k0);
        As[lk + 0][lr] = av.x; As[lk + 1][lr] = av.y;
        As[lk + 2][lr] = av.z; As[lk + 3][lr] = av.w;
        Bs[lk + 0][lr] = bv.x; Bs[lk + 1][lr] = bv.y;
        Bs[lk + 2][lr] = bv.z; Bs[lk + 3][lr] = bv.w;
        __syncthreads();

        #pragma unroll
        for (int kk = 0; kk < 8; kk++) {
            float a[8], b[8];
            *(float4*)&a[0] = *(const float4*)&As[kk][ty * 8 + 0];
            *(float4*)&a[4] = *(const float4*)&As[kk][ty * 8 + 4];
            *(float4*)&b[0] = *(const float4*)&Bs[kk][tx * 8 + 0];
            *(float4*)&b[4] = *(const float4*)&Bs[kk][tx * 8 + 4];
            #pragma unroll
            for (int i = 0; i < 8; i++)
                #pragma unroll
                for (int j = 0; j < 8; j++)
                    acc[i][j] = fmaf(a[i], b[j], acc[i][j]);
        }
        __syncthreads();
    }

    float* Cb = C + (size_t)(blockIdx.y * 128 + ty * 8) * Nn + blockIdx.x * 128 + tx * 8;
    #pragma unroll
    for (int i = 0; i < 8; i++) {
        float4 o0, o1;
        o0.x = alpha * acc[i][0]; o0.y = alpha * acc[i][1];
        o0.z = alpha * acc[i][2]; o0.w = alpha * acc[i][3];
        o1.x = alpha * acc[i][4]; o1.y = alpha * acc[i][5];
        o1.z = alpha * acc[i][6]; o1.w = alpha * acc[i][7];
        *(float4*)(Cb + (size_t)i * Nn + 0) = o0;
        *(float4*)(Cb + (size_t)i * Nn + 4) = o1;
    }
}

// =====================================================================
// Banded logits: S[i][j-i+249] = Q[i,:] . K[j,:]  for |i-j| <= 249
// block = (jt 0..8, it 0..127); 64x64 tile, BK=16, 256 thr, 4x4/thread
// =====================================================================
__global__ __launch_bounds__(256) void qk_band_kernel()
{
    __shared__ float Qs[16][64];
    __shared__ float Ks[16][64];
    const int t  = threadIdx.x;
    const int tx = t & 15;
    const int ty = t >> 4;
    const int i0 = blockIdx.y * 64;
    const int j0 = i0 - APW + blockIdx.x * 64;

    const int lr = t >> 2;          // 0..63
    const int lk = (t & 3) << 2;    // 0,4,8,12

    float acc[4][4] = {};

    for (int k0 = 0; k0 < DDIM; k0 += 16) {
        float4 qv = *(const float4*)(g_Q + (size_t)(i0 + lr) * DDIM + k0 + lk);
        const int jr = j0 + lr;
        float4 kv = make_float4(0.f, 0.f, 0.f, 0.f);
        if (jr >= 0 && jr < NTOK)
            kv = *(const float4*)(g_K + (size_t)jr * DDIM + k0 + lk);
        Qs[lk + 0][lr] = qv.x; Qs[lk + 1][lr] = qv.y;
        Qs[lk + 2][lr] = qv.z; Qs[lk + 3][lr] = qv.w;
        Ks[lk + 0][lr] = kv.x; Ks[lk + 1][lr] = kv.y;
        Ks[lk + 2][lr] = kv.z; Ks[lk + 3][lr] = kv.w;
        __syncthreads();

        #pragma unroll
        for (int kk = 0; kk < 16; kk++) {
            float4 qq = *(const float4*)&Qs[kk][ty * 4];
            float4 kf = *(const float4*)&Ks[kk][tx * 4];
            float q[4] = {qq.x, qq.y, qq.z, qq.w};
            float b[4] = {kf.x, kf.y, kf.z, kf.w};
            #pragma unroll
            for (int a = 0; a < 4; a++)
                #pragma unroll
                for (int bb = 0; bb < 4; bb++)
                    acc[a][bb] = fmaf(q[a], b[bb], acc[a][bb]);
        }
        __syncthreads();
    }

    #pragma unroll
    for (int a = 0; a < 4; a++) {
        const int i = i0 + ty * 4 + a;
        #pragma unroll
        for (int b = 0; b < 4; b++) {
            const int j  = j0 + tx * 4 + b;
            const int tt = j - i + APW;
            if (j >= 0 && j < NTOK && (unsigned)tt <= (unsigned)(2 * APW))
                g_S[(size_t)i * BANDW + tt] = acc[a][b];
        }
    }
}

// =====================================================================
// Per-row band softmax. Normalizes g_S in place; optionally writes the
// band slice of the full att_weights output (rest already memset to 0).
// block = row i, 256 threads (each covers slots t and t+256)
// =====================================================================
__global__ __launch_bounds__(256) void softmax_band_kernel(float* __restrict__ d_att,
                                                           int write_att)
{
    const int i = blockIdx.x;
    const int t = threadIdx.x;
    const int t_lo = (i < APW) ? (APW - i) : 0;
    const int jmax = (i + APW < NTOK - 1) ? (i + APW) : (NTOK - 1);
    const int t_hi = jmax - i + APW;

    float* row = g_S + (size_t)i * BANDW;
    const int t0 = t, t1 = t + 256;
    float v0 = (t0 >= t_lo && t0 <= t_hi) ? row[t0] : -INFINITY;
    float v1 = (t1 >= t_lo && t1 <= t_hi) ? row[t1] : -INFINITY;

    __shared__ float shm[8];
    __shared__ float shs[8];
    const int lane = t & 31, warp = t >> 5;

    // ---- block max ----
    float m = fmaxf(v0, v1);
    #pragma unroll
    for (int o = 16; o > 0; o >>= 1) m = fmaxf(m, __shfl_xor_sync(0xffffffffu, m, o));
    if (lane == 0) shm[warp] = m;
    __syncthreads();
    if (warp == 0) {
        float mm = (lane < 8) ? shm[lane] : -INFINITY;
        #pragma unroll
        for (int o = 4; o > 0; o >>= 1) mm = fmaxf(mm, __shfl_xor_sync(0xffffffffu, mm, o));
        if (lane == 0) shm[0] = mm;
    }
    __syncthreads();
    const float M = shm[0];

    // ---- exp + block sum ----
    const float e0 = expf(v0 - M);      // -inf -> 0
    const float e1 = expf(v1 - M);
    float s = e0 + e1;
    #pragma unroll
    for (int o = 16; o > 0; o >>= 1) s += __shfl_xor_sync(0xffffffffu, s, o);
    if (lane == 0) shs[warp] = s;
    __syncthreads();
    if (warp == 0) {
        float ss = (lane < 8) ? shs[lane] : 0.f;
        #pragma unroll
        for (int o = 4; o > 0; o >>= 1) ss += __shfl_xor_sync(0xffffffffu, ss, o);
        if (lane == 0) shs[0] = ss;
    }
    __syncthreads();
    const float inv = 1.0f / shs[0];

    if (t0 >= t_lo && t0 <= t_hi) {
        const float w = e0 * inv;
        row[t0] = w;
        if (write_att) d_att[(size_t)i * NTOK + (i - APW + t0)] = w;
    }
    if (t1 >= t_lo && t1 <= t_hi) {
        const float w = e1 * inv;
        row[t1] = w;
        if (write_att) d_att[(size_t)i * NTOK + (i - APW + t1)] = w;
    }
}

// =====================================================================
// y0[j,d] = sum_i att[i,j] * V[i,d]   (att^T @ V, band-limited in i)
// block = (dt 0..15, jt 0..127); 64x64 tile, chunk 16 over i, 4x4/thread
// =====================================================================
__global__ __launch_bounds__(256) void attv_kernel()
{
    __shared__ float As[16][64];    // As[k][j_local] = att(iStart+ic+k, j0+j_local)
    __shared__ float Vs[16][64];    // Vs[k][d_local]
    const int t  = threadIdx.x;
    const int tx = t & 15;
    const int ty = t >> 4;
    const int j0 = blockIdx.y * 64;
    const int d0 = blockIdx.x * 64;
    const int iStart = j0 - APW;

    const int lrA = t >> 4;          // 0..15
    const int lcA = (t & 15) << 2;   // 0..60

    float acc[4][4] = {};

    for (int ic = 0; ic < 576; ic += 16) {
        const int i = iStart + ic + lrA;
        const bool iok = (i >= 0 && i < NTOK);

        #pragma unroll
        for (int c = 0; c < 4; c++) {
            const int j  = j0 + lcA + c;
            const int tt = j - i + APW;
            float a = 0.f;
            if (iok && (unsigned)tt <= (unsigned)(2 * APW))
                a = g_S[(size_t)i * BANDW + tt];
            As[lrA][lcA + c] = a;
        }
        float4 vv = make_float4(0.f, 0.f, 0.f, 0.f);
        if (iok) vv = *(const float4*)(g_V + (size_t)i * DDIM + d0 + lcA);
        *(float4*)&Vs[lrA][lcA] = vv;
        __syncthreads();

        #pragma unroll
        for (int kk = 0; kk < 16; kk++) {
            float4 aa = *(const float4*)&As[kk][ty * 4];
            float4 vd = *(const float4*)&Vs[kk][tx * 4];
            float a[4] = {aa.x, aa.y, aa.z, aa.w};
            float v[4] = {vd.x, vd.y, vd.z, vd.w};
            #pragma unroll
            for (int p = 0; p < 4; p++)
                #pragma unroll
                for (int q = 0; q < 4; q++)
                    acc[p][q] = fmaf(a[p], v[q], acc[p][q]);
        }
        __syncthreads();
    }

    #pragma unroll
    for (int p = 0; p < 4; p++) {
        float4 o;
        o.x = acc[p][0]; o.y = acc[p][1]; o.z = acc[p][2]; o.w = acc[p][3];
        *(float4*)(g_Y0 + (size_t)(j0 + ty * 4 + p) * DDIM + d0 + tx * 4) = o;
    }
}

// =====================================================================
extern "C" void kernel_launch(void* const* d_in, const int* in_sizes, int n_in,
                              void* d_out, int out_size)
{
    const float* x  = (const float*)d_in[0];
    const float* Wq = (const float*)d_in[1];
    const float* Wk = (const float*)d_in[2];
    const float* Wv = (const float*)d_in[3];
    const float* Wo = (const float*)d_in[4];

    float *Qp, *Kp, *Vp, *Y0p;
    cudaGetSymbolAddress((void**)&Qp,  g_Q);
    cudaGetSymbolAddress((void**)&Kp,  g_K);
    cudaGetSymbolAddress((void**)&Vp,  g_V);
    cudaGetSymbolAddress((void**)&Y0p, g_Y0);

    const size_t yel = (size_t)NTOK * DDIM;        // 8388608
    const size_t ael = (size_t)NTOK * NTOK;        // 67108864
    float* d_y;
    float* d_att;
    int write_att;
    if ((size_t)out_size >= yel + ael) {           // tuple (y, att) flattened
        d_y = (float*)d_out;
        d_att = (float*)d_out + yel;
        write_att = 1;
    } else if ((size_t)out_size >= ael) {          // att only (defensive)
        d_y = Qp;                                  // discard y into scratch
        d_att = (float*)d_out;
        write_att = 1;
    } else {                                       // y only
        d_y = (float*)d_out;
        d_att = nullptr;
        write_att = 0;
    }

    const dim3 gGemm(DDIM / 128, NTOK / 128);      // (8, 64)

    // Projections
    gemm_nt_128<<<gGemm, 256>>>(x, Wq, Qp, NTOK, DDIM, DDIM, 0.06f);
    gemm_nt_128<<<gGemm, 256>>>(x, Wk, Kp, NTOK, DDIM, DDIM, 1.0f);
    gemm_nt_128<<<gGemm, 256>>>(x, Wv, Vp, NTOK, DDIM, DDIM, 1.0f);

    // Banded logits
    qk_band_kernel<<<dim3(9, NTOK / 64), 256>>>();

    // Zero the full att_weights output (out-of-band entries), then softmax
    if (write_att)
        cudaMemsetAsync(d_att, 0, ael * sizeof(float));
    softmax_band_kernel<<<NTOK, 256>>>(d_att, write_att);

    // y0 = att^T @ V
    attv_kernel<<<dim3(DDIM / 64, NTOK / 64), 256>>>();

    // y = y0 @ Wo^T
    gemm_nt_128<<<gGemm, 256>>>(Y0p, Wo, d_y, NTOK, DDIM, DDIM, 1.0f);
}

// round 2
// speedup vs baseline: 1.8867x; 1.8867x over previous
#include <cuda_runtime.h>
#include <math.h>
#include <stdint.h>

#define NTOK 8192
#define DDIM 1024
#define APW  249            // APPERTURE - 1 : band is |i - j| <= 249
#define BANDW 512           // padded band width; valid t = j - i + 249 in [0, 498]

// ---------------- scratch (static device arrays; no allocation) ----------------
__device__ float g_Q [(size_t)NTOK * DDIM];
__device__ float g_K [(size_t)NTOK * DDIM];
__device__ float g_V [(size_t)NTOK * DDIM];
__device__ float g_Y0[(size_t)NTOK * DDIM];
__device__ float g_S [(size_t)NTOK * BANDW];

// =====================================================================
// tf32 helpers
// =====================================================================
__device__ __forceinline__ uint32_t f2tf32(float f) {
    uint32_t u;
    asm("cvt.rna.tf32.f32 %0, %1;" : "=r"(u) : "f"(f));
    return u;
}

__device__ __forceinline__ void mma_tf32(float c[4], const uint32_t a[4], const uint32_t b[2]) {
    asm volatile(
        "mma.sync.aligned.m16n8k8.row.col.f32.tf32.tf32.f32 "
        "{%0,%1,%2,%3}, {%4,%5,%6,%7}, {%8,%9}, {%0,%1,%2,%3};"
        : "+f"(c[0]), "+f"(c[1]), "+f"(c[2]), "+f"(c[3])
        : "r"(a[0]), "r"(a[1]), "r"(a[2]), "r"(a[3]), "r"(b[0]), "r"(b[1]));
}

// =====================================================================
// C[M,Nn] = alpha * A[M,K] @ B[Nn,K]^T  (row-major), tf32 tensor cores.
// Block tile 128x128, BK=32, 256 threads = 8 warps, warp tile 64x32.
// Requires M%128==0, Nn%128==0, K%32==0.
// =====================================================================
#define BM 128
#define BN 128
#define BK 32
#define LDS_STRIDE 36      // BK + 4 pad: bank = (row*4 + k) % 32 -> conflict-free frags

__global__ __launch_bounds__(256) void gemm_tf32_nt(
    const float* __restrict__ A, const float* __restrict__ B,
    float* __restrict__ C, int M, int Nn, int K, float alpha)
{
    __shared__ uint32_t As[BM * LDS_STRIDE];
    __shared__ uint32_t Bs[BN * LDS_STRIDE];

    const int t    = threadIdx.x;
    const int warp = t >> 5;
    const int lane = t & 31;
    const int g    = lane >> 2;     // group id 0..7
    const int tig  = lane & 3;      // thread-in-group 0..3

    const int wm = warp >> 2;       // 0..1 : m position (64 each)
    const int wn = warp & 3;        // 0..3 : n position (32 each)

    const int rowA0 = blockIdx.y * BM;
    const int rowB0 = blockIdx.x * BN;

    // gmem tile load mapping: 128 rows x 32 cols; thread -> row = t>>1,
    // 16 consecutive floats starting at (t&1)*16.
    const int lr = t >> 1;
    const int lc = (t & 1) << 4;

    const float* Ag = A + (size_t)(rowA0 + lr) * K + lc;
    const float* Bg = B + (size_t)(rowB0 + lr) * K + lc;

    float acc[4][4][4];
    #pragma unroll
    for (int i = 0; i < 4; i++)
        #pragma unroll
        for (int j = 0; j < 4; j++)
            #pragma unroll
            for (int c = 0; c < 4; c++) acc[i][j][c] = 0.f;

    float4 pa[4], pb[4];
    // prologue: prefetch tile 0
    #pragma unroll
    for (int i = 0; i < 4; i++) {
        pa[i] = *(const float4*)(Ag + i * 4);
        pb[i] = *(const float4*)(Bg + i * 4);
    }

    for (int k0 = 0; k0 < K; k0 += BK) {
        // store prefetched tile (cvt to tf32)
        #pragma unroll
        for (int i = 0; i < 4; i++) {
            uint32_t* as = &As[lr * LDS_STRIDE + lc + i * 4];
            as[0] = f2tf32(pa[i].x); as[1] = f2tf32(pa[i].y);
            as[2] = f2tf32(pa[i].z); as[3] = f2tf32(pa[i].w);
            uint32_t* bs = &Bs[lr * LDS_STRIDE + lc + i * 4];
            bs[0] = f2tf32(pb[i].x); bs[1] = f2tf32(pb[i].y);
            bs[2] = f2tf32(pb[i].z); bs[3] = f2tf32(pb[i].w);
        }
        __syncthreads();

        // prefetch next tile while computing
        if (k0 + BK < K) {
            #pragma unroll
            for (int i = 0; i < 4; i++) {
                pa[i] = *(const float4*)(Ag + k0 + BK + i * 4);
                pb[i] = *(const float4*)(Bg + k0 + BK + i * 4);
            }
        }

        #pragma unroll
        for (int k8 = 0; k8 < 4; k8++) {
            const int kk = k8 * 8 + tig;
            uint32_t af[4][4], bf[4][2];
            #pragma unroll
            for (int fm = 0; fm < 4; fm++) {
                const int m = wm * 64 + fm * 16 + g;
                af[fm][0] = As[(m    ) * LDS_STRIDE + kk    ];
                af[fm][1] = As[(m + 8) * LDS_STRIDE + kk    ];
                af[fm][2] = As[(m    ) * LDS_STRIDE + kk + 4];
                af[fm][3] = As[(m + 8) * LDS_STRIDE + kk + 4];
            }
            #pragma unroll
            for (int fn = 0; fn < 4; fn++) {
                const int n = wn * 32 + fn * 8 + g;
                bf[fn][0] = Bs[n * LDS_STRIDE + kk    ];
                bf[fn][1] = Bs[n * LDS_STRIDE + kk + 4];
            }
            #pragma unroll
            for (int fm = 0; fm < 4; fm++)
                #pragma unroll
                for (int fn = 0; fn < 4; fn++)
                    mma_tf32(acc[fm][fn], af[fm], bf[fn]);
        }
        __syncthreads();
    }

    // epilogue
    #pragma unroll
    for (int fm = 0; fm < 4; fm++) {
        const int m0 = rowA0 + wm * 64 + fm * 16 + g;
        #pragma unroll
        for (int fn = 0; fn < 4; fn++) {
            const int n0 = rowB0 + wn * 32 + fn * 8 + 2 * tig;
            float2 v01 = make_float2(alpha * acc[fm][fn][0], alpha * acc[fm][fn][1]);
            float2 v23 = make_float2(alpha * acc[fm][fn][2], alpha * acc[fm][fn][3]);
            *(float2*)(C + (size_t)m0 * Nn + n0)       = v01;
            *(float2*)(C + (size_t)(m0 + 8) * Nn + n0) = v23;
        }
    }
}

// =====================================================================
// Banded logits: S[i][j-i+249] = Q[i,:] . K[j,:]  for |i-j| <= 249
// block = (jt 0..8, it 0..127); 64x64 tile, BK=16, 256 thr, 4x4/thread
// =====================================================================
__global__ __launch_bounds__(256) void qk_band_kernel()
{
    __shared__ float Qs[16][64];
    __shared__ float Ks[16][64];
    const int t  = threadIdx.x;
    const int tx = t & 15;
    const int ty = t >> 4;
    const int i0 = blockIdx.y * 64;
    const int j0 = i0 - APW + blockIdx.x * 64;

    const int lr = t >> 2;          // 0..63
    const int lk = (t & 3) << 2;    // 0,4,8,12

    float acc[4][4] = {};

    for (int k0 = 0; k0 < DDIM; k0 += 16) {
        float4 qv = *(const float4*)(g_Q + (size_t)(i0 + lr) * DDIM + k0 + lk);
        const int jr = j0 + lr;
        float4 kv = make_float4(0.f, 0.f, 0.f, 0.f);
        if (jr >= 0 && jr < NTOK)
            kv = *(const float4*)(g_K + (size_t)jr * DDIM + k0 + lk);
        Qs[lk + 0][lr] = qv.x; Qs[lk + 1][lr] = qv.y;
        Qs[lk + 2][lr] = qv.z; Qs[lk + 3][lr] = qv.w;
        Ks[lk + 0][lr] = kv.x; Ks[lk + 1][lr] = kv.y;
        Ks[lk + 2][lr] = kv.z; Ks[lk + 3][lr] = kv.w;
        __syncthreads();

        #pragma unroll
        for (int kk = 0; kk < 16; kk++) {
            float4 qq = *(const float4*)&Qs[kk][ty * 4];
            float4 kf = *(const float4*)&Ks[kk][tx * 4];
            float q[4] = {qq.x, qq.y, qq.z, qq.w};
            float b[4] = {kf.x, kf.y, kf.z, kf.w};
            #pragma unroll
            for (int a = 0; a < 4; a++)
                #pragma unroll
                for (int bb = 0; bb < 4; bb++)
                    acc[a][bb] = fmaf(q[a], b[bb], acc[a][bb]);
        }
        __syncthreads();
    }

    #pragma unroll
    for (int a = 0; a < 4; a++) {
        const int i = i0 + ty * 4 + a;
        #pragma unroll
        for (int b = 0; b < 4; b++) {
            const int j  = j0 + tx * 4 + b;
            const int tt = j - i + APW;
            if (j >= 0 && j < NTOK && (unsigned)tt <= (unsigned)(2 * APW))
                g_S[(size_t)i * BANDW + tt] = acc[a][b];
        }
    }
}

// =====================================================================
// Per-row band softmax. Normalizes g_S in place; optionally writes the
// band slice of the full att_weights output (rest already memset to 0).
// block = row i, 256 threads (each covers slots t and t+256)
// =====================================================================
__global__ __launch_bounds__(256) void softmax_band_kernel(float* __restrict__ d_att,
                                                           int write_att)
{
    const int i = blockIdx.x;
    const int t = threadIdx.x;
    const int t_lo = (i < APW) ? (APW - i) : 0;
    const int jmax = (i + APW < NTOK - 1) ? (i + APW) : (NTOK - 1);
    const int t_hi = jmax - i + APW;

    float* row = g_S + (size_t)i * BANDW;
    const int t0 = t, t1 = t + 256;
    float v0 = (t0 >= t_lo && t0 <= t_hi) ? row[t0] : -INFINITY;
    float v1 = (t1 >= t_lo && t1 <= t_hi) ? row[t1] : -INFINITY;

    __shared__ float shm[8];
    __shared__ float shs[8];
    const int lane = t & 31, warp = t >> 5;

    // ---- block max ----
    float m = fmaxf(v0, v1);
    #pragma unroll
    for (int o = 16; o > 0; o >>= 1) m = fmaxf(m, __shfl_xor_sync(0xffffffffu, m, o));
    if (lane == 0) shm[warp] = m;
    __syncthreads();
    if (warp == 0) {
        float mm = (lane < 8) ? shm[lane] : -INFINITY;
        #pragma unroll
        for (int o = 4; o > 0; o >>= 1) mm = fmaxf(mm, __shfl_xor_sync(0xffffffffu, mm, o));
        if (lane == 0) shm[0] = mm;
    }
    __syncthreads();
    const float M = shm[0];

    // ---- exp + block sum ----
    const float e0 = expf(v0 - M);      // -inf -> 0
    const float e1 = expf(v1 - M);
    float s = e0 + e1;
    #pragma unroll
    for (int o = 16; o > 0; o >>= 1) s += __shfl_xor_sync(0xffffffffu, s, o);
    if (lane == 0) shs[warp] = s;
    __syncthreads();
    if (warp == 0) {
        float ss = (lane < 8) ? shs[lane] : 0.f;
        #pragma unroll
        for (int o = 4; o > 0; o >>= 1) ss += __shfl_xor_sync(0xffffffffu, ss, o);
        if (lane == 0) shs[0] = ss;
    }
    __syncthreads();
    const float inv = 1.0f / shs[0];

    if (t0 >= t_lo && t0 <= t_hi) {
        const float w = e0 * inv;
        row[t0] = w;
        if (write_att) d_att[(size_t)i * NTOK + (i - APW + t0)] = w;
    }
    if (t1 >= t_lo && t1 <= t_hi) {
        const float w = e1 * inv;
        row[t1] = w;
        if (write_att) d_att[(size_t)i * NTOK + (i - APW + t1)] = w;
    }
}

// =====================================================================
// y0[j,d] = sum_i att[i,j] * V[i,d]   (att^T @ V, band-limited in i)
// block = (dt 0..15, jt 0..127); 64x64 tile, chunk 16 over i, 4x4/thread
// =====================================================================
__global__ __launch_bounds__(256) void attv_kernel()
{
    __shared__ float As[16][64];    // As[k][j_local] = att(iStart+ic+k, j0+j_local)
    __shared__ float Vs[16][64];    // Vs[k][d_local]
    const int t  = threadIdx.x;
    const int tx = t & 15;
    const int ty = t >> 4;
    const int j0 = blockIdx.y * 64;
    const int d0 = blockIdx.x * 64;
    const int iStart = j0 - APW;

    const int lrA = t >> 4;          // 0..15
    const int lcA = (t & 15) << 2;   // 0..60

    float acc[4][4] = {};

    for (int ic = 0; ic < 576; ic += 16) {
        const int i = iStart + ic + lrA;
        const bool iok = (i >= 0 && i < NTOK);

        #pragma unroll
        for (int c = 0; c < 4; c++) {
            const int j  = j0 + lcA + c;
            const int tt = j - i + APW;
            float a = 0.f;
            if (iok && (unsigned)tt <= (unsigned)(2 * APW))
                a = g_S[(size_t)i * BANDW + tt];
            As[lrA][lcA + c] = a;
        }
        float4 vv = make_float4(0.f, 0.f, 0.f, 0.f);
        if (iok) vv = *(const float4*)(g_V + (size_t)i * DDIM + d0 + lcA);
        *(float4*)&Vs[lrA][lcA] = vv;
        __syncthreads();

        #pragma unroll
        for (int kk = 0; kk < 16; kk++) {
            float4 aa = *(const float4*)&As[kk][ty * 4];
            float4 vd = *(const float4*)&Vs[kk][tx * 4];
            float a[4] = {aa.x, aa.y, aa.z, aa.w};
            float v[4] = {vd.x, vd.y, vd.z, vd.w};
            #pragma unroll
            for (int p = 0; p < 4; p++)
                #pragma unroll
                for (int q = 0; q < 4; q++)
                    acc[p][q] = fmaf(a[p], v[q], acc[p][q]);
        }
        __syncthreads();
    }

    #pragma unroll
    for (int p = 0; p < 4; p++) {
        float4 o;
        o.x = acc[p][0]; o.y = acc[p][1]; o.z = acc[p][2]; o.w = acc[p][3];
        *(float4*)(g_Y0 + (size_t)(j0 + ty * 4 + p) * DDIM + d0 + tx * 4) = o;
    }
}

// =====================================================================
extern "C" void kernel_launch(void* const* d_in, const int* in_sizes, int n_in,
                              void* d_out, int out_size)
{
    const float* x  = (const float*)d_in[0];
    const float* Wq = (const float*)d_in[1];
    const float* Wk = (const float*)d_in[2];
    const float* Wv = (const float*)d_in[3];
    const float* Wo = (const float*)d_in[4];

    float *Qp, *Kp, *Vp, *Y0p;
    cudaGetSymbolAddress((void**)&Qp,  g_Q);
    cudaGetSymbolAddress((void**)&Kp,  g_K);
    cudaGetSymbolAddress((void**)&Vp,  g_V);
    cudaGetSymbolAddress((void**)&Y0p, g_Y0);

    const size_t yel = (size_t)NTOK * DDIM;        // 8388608
    const size_t ael = (size_t)NTOK * NTOK;        // 67108864
    float* d_y;
    float* d_att;
    int write_att;
    if ((size_t)out_size >= yel + ael) {           // tuple (y, att) flattened
        d_y = (float*)d_out;
        d_att = (float*)d_out + yel;
        write_att = 1;
    } else if ((size_t)out_size >= ael) {          // att only (defensive)
        d_y = Qp;                                  // discard y into scratch
        d_att = (float*)d_out;
        write_att = 1;
    } else {                                       // y only
        d_y = (float*)d_out;
        d_att = nullptr;
        write_att = 0;
    }

    const dim3 gGemm(DDIM / BN, NTOK / BM);        // (8, 64)

    // Projections (tf32 tensor cores)
    gemm_tf32_nt<<<gGemm, 256>>>(x, Wq, Qp, NTOK, DDIM, DDIM, 0.06f);
    gemm_tf32_nt<<<gGemm, 256>>>(x, Wk, Kp, NTOK, DDIM, DDIM, 1.0f);
    gemm_tf32_nt<<<gGemm, 256>>>(x, Wv, Vp, NTOK, DDIM, DDIM, 1.0f);

    // Banded logits
    qk_band_kernel<<<dim3(9, NTOK / 64), 256>>>();

    // Zero the full att_weights output (out-of-band entries), then softmax
    if (write_att)
        cudaMemsetAsync(d_att, 0, ael * sizeof(float));
    softmax_band_kernel<<<NTOK, 256>>>(d_att, write_att);

    // y0 = att^T @ V
    attv_kernel<<<dim3(DDIM / 64, NTOK / 64), 256>>>();

    // y = y0 @ Wo^T (tf32 tensor cores)
    gemm_tf32_nt<<<gGemm, 256>>>(Y0p, Wo, d_y, NTOK, DDIM, DDIM, 1.0f);
}